// round 1
// baseline (speedup 1.0000x reference)
#include <cuda_runtime.h>
#include <math.h>

#define SEQ_LEN 16384
#define BATCH   32
#define DM      128
#define HN      256
#define THRESH  0.001f

#define RPB   128                 // rows per block
#define NBLK  (SEQ_LEN / RPB)     // 128 blocks
#define NST   130                 // node smem row stride (floats, padded)
#define HST   258                 // hyper smem row stride (floats, padded)

#define NODE_SH_F (DM * NST)      // 16640 floats
#define HYP_SH_F  (DM * HST)      // 33024 floats
#define SMEM_F    (NODE_SH_F + HYP_SH_F + RPB)
#define SMEM_B    (SMEM_F * 4)    // 199168 bytes

__device__ __forceinline__ unsigned long long splat2(float x) {
    unsigned r = __float_as_uint(x);
    unsigned long long d;
    asm("mov.b64 %0, {%1, %2};" : "=l"(d) : "r"(r), "r"(r));
    return d;
}

__device__ __forceinline__ void fma2(unsigned long long& acc,
                                     unsigned long long a, unsigned long long b) {
    asm("fma.rn.f32x2 %0, %1, %2, %0;" : "+l"(acc) : "l"(a), "l"(b));
}

// One row of the output: softmax + exact top-8 (jax tie semantics: equal values ->
// lower hyperedge index wins) + threshold. All 256 h values for this row live in
// this warp: lane holds h = lane + 32*j, j=0..7.
__device__ __forceinline__ void process_row(int row, const float* vin, float m,
                                            int lane, float* __restrict__ out)
{
    float v[8];
    unsigned ub[8];
#pragma unroll
    for (int j = 0; j < 8; ++j) {
        float x = fmaxf(vin[j], 0.0f) * m;   // relu then mask-penalty scale
        v[j] = x;
        // values are >= 0, so float bits are order-monotone; force -0 -> bits 0
        ub[j] = (x == 0.0f) ? 0u : __float_as_uint(x);
    }

    // row max (bitwise monotone for non-negative floats)
    unsigned lmb = ub[0];
#pragma unroll
    for (int j = 1; j < 8; ++j) lmb = (ub[j] > lmb) ? ub[j] : lmb;
    unsigned gmb = __reduce_max_sync(0xffffffffu, lmb);
    float rowmax = __uint_as_float(gmb);

    // softmax denominator
    float e[8];
    float ls = 0.0f;
#pragma unroll
    for (int j = 0; j < 8; ++j) { e[j] = expf(v[j] - rowmax); ls += e[j]; }
#pragma unroll
    for (int o = 16; o; o >>= 1) ls += __shfl_xor_sync(0xffffffffu, ls, o);

    // exact top-8 selection: 8x warp argmax over (value, lowest h on ties)
    unsigned selmask = 0;
    int bj = 0; unsigned bv = ub[0];
#pragma unroll
    for (int j = 1; j < 8; ++j) if (ub[j] > bv) { bv = ub[j]; bj = j; }
#pragma unroll 1
    for (int it = 0; it < 8; ++it) {
        unsigned cand = (bj >= 0) ? bv : 0u;
        unsigned g  = __reduce_max_sync(0xffffffffu, cand);
        unsigned hc = (bj >= 0 && cand == g) ? (unsigned)(bj * 32 + lane) : 0xffffffffu;
        unsigned gh = __reduce_min_sync(0xffffffffu, hc);
        if (hc == gh) {
            selmask |= (1u << bj);
            bv = 0u; bj = -1;
#pragma unroll
            for (int j = 0; j < 8; ++j)
                if (!(selmask & (1u << j)) && (bj < 0 || ub[j] > bv)) { bv = ub[j]; bj = j; }
        }
    }

    float* op = out + (size_t)row * HN + lane;
#pragma unroll
    for (int j = 0; j < 8; ++j) {
        float soft = e[j] / ls;
        op[32 * j] = (((selmask >> j) & 1u) && (soft > THRESH)) ? 1.0f : 0.0f;
    }
}

__global__ __launch_bounds__(256, 1)
void hg_kernel(const float* __restrict__ mask, const float* __restrict__ node,
               const float* __restrict__ hyper, float* __restrict__ out)
{
    extern __shared__ float sm[];
    float* node_sh = sm;                          // [DM][NST], node_sh[d*NST + r]
    float* hyp_sh  = sm + NODE_SH_F;              // [DM][HST], hyp_sh[d*HST + h]
    float* mp_sh   = sm + NODE_SH_F + HYP_SH_F;   // [RPB]

    const int t  = threadIdx.x;
    const int n0 = blockIdx.x * RPB;

    // mask penalty: mean over batch for this block's rows (sequential b order)
    if (t < RPB) {
        float s = 0.0f;
        const float* mc = mask + n0 + t;
#pragma unroll
        for (int b = 0; b < BATCH; ++b) s += mc[b * SEQ_LEN];
        mp_sh[t] = s / 32.0f;
    }
    // node tile, transposed (k-major): coalesced global reads
    for (int i = t; i < RPB * DM; i += 256) {
        int r = i >> 7, d = i & (DM - 1);
        node_sh[d * NST + r] = node[(size_t)(n0 + r) * DM + d];
    }
    // full hyper matrix, transposed (k-major)
    for (int i = t; i < HN * DM; i += 256) {
        int h = i >> 7, d = i & (DM - 1);
        hyp_sh[d * HST + h] = hyper[i];
    }
    __syncthreads();

    const int lane = t & 31;
    const int w    = t >> 5;

    // warp w owns rows [16w, 16w+16); lane owns h = lane + 32j.
    // acc[j][i] = f32x2 pair { dot(row 16w+2i, h), dot(row 16w+2i+1, h) },
    // each component is a plain sequential fp32 sum over k.
    unsigned long long acc[8][8];
#pragma unroll
    for (int j = 0; j < 8; ++j)
#pragma unroll
        for (int i = 0; i < 8; ++i) acc[j][i] = 0ull;

    const float* np = node_sh + 16 * w;   // + k*NST ; rows pairs at 2i (8B aligned)
    const float* hp = hyp_sh + lane;      // + k*HST + 32j ; bank == lane (conflict-free)
#pragma unroll 2
    for (int k = 0; k < DM; ++k) {
        unsigned long long nv[8];
#pragma unroll
        for (int i = 0; i < 8; ++i)
            nv[i] = *reinterpret_cast<const unsigned long long*>(np + 2 * i);
        unsigned long long hs[8];
#pragma unroll
        for (int j = 0; j < 8; ++j) hs[j] = splat2(hp[32 * j]);
#pragma unroll
        for (int j = 0; j < 8; ++j)
#pragma unroll
            for (int i = 0; i < 8; ++i) fma2(acc[j][i], hs[j], nv[i]);
        np += NST;
        hp += HST;
    }

    // epilogue: unrolled over row pairs so acc indexing stays static (no spills)
#pragma unroll
    for (int rp = 0; rp < 8; ++rp) {
        float vlo[8], vhi[8];
#pragma unroll
        for (int j = 0; j < 8; ++j) {
            vlo[j] = __uint_as_float((unsigned)(acc[j][rp] & 0xffffffffull));
            vhi[j] = __uint_as_float((unsigned)(acc[j][rp] >> 32));
        }
        int r0 = 16 * w + 2 * rp;
        process_row(n0 + r0,     vlo, mp_sh[r0],     lane, out);
        process_row(n0 + r0 + 1, vhi, mp_sh[r0 + 1], lane, out);
    }
}

extern "C" void kernel_launch(void* const* d_in, const int* in_sizes, int n_in,
                              void* d_out, int out_size)
{
    // metadata order: [0] features (unused), [1] mask, [2] node_embeds, [3] hyper_embeds
    const float* mask  = (const float*)d_in[1];
    const float* node  = (const float*)d_in[2];
    const float* hyper = (const float*)d_in[3];
    float* out = (float*)d_out;

    cudaFuncSetAttribute(hg_kernel, cudaFuncAttributeMaxDynamicSharedMemorySize, SMEM_B);
    hg_kernel<<<NBLK, 256, SMEM_B>>>(mask, node, hyper, out);
}